// round 1
// baseline (speedup 1.0000x reference)
#include <cuda_runtime.h>

#define N_SAMP   16384
#define D_IN     64
#define H_DIM    256
#define MT       32          // samples per block
#define NTHREADS 256
#define NBLOCKS  (N_SAMP / MT)

// ---- shared memory layout (float offsets) ----
#define SW1_OFF  0                               // W1 staged [p][65]  : 256*65
#define SZ1_OFF  (SW1_OFF + 256 * 65)            // z1   [MT][256]
#define SY1_OFF  (SZ1_OFF + MT * H_DIM)          // y1 -> later v
#define SU_OFF   (SY1_OFF + MT * H_DIM)          // u  -> later grad [MT][64]
#define SW2_OFF  (SU_OFF + MT * H_DIM)           // W2 tile: max(256*33, 32*257)=8448
#define SS_OFF   (SW2_OFF + 8448)                // S tile [MT][64]
#define SB1_OFF  (SS_OFF + MT * D_IN)
#define SB2_OFF  (SB1_OFF + 256)
#define SW3_OFF  (SB2_OFF + 256)
#define SNN_OFF  (SW3_OFF + 256)                 // nn_out accum [MT]
#define SMEM_FLOATS (SNN_OFF + 32)
#define SMEM_BYTES  (SMEM_FLOATS * 4)            // 210048 B

__global__ __launch_bounds__(NTHREADS, 1)
void learnerct_fused(const float* __restrict__ S,
                     const float* __restrict__ Sdot,
                     const float* __restrict__ W1,
                     const float* __restrict__ b1,
                     const float* __restrict__ W2,
                     const float* __restrict__ b2,
                     const float* __restrict__ W3,
                     float* __restrict__ out)
{
    extern __shared__ float sm[];
    const int tid = threadIdx.x;
    const int m0  = blockIdx.x * MT;

    // ---------------- staging ----------------
    // W1 [256][64] row-major -> sm[SW1_OFF + p*65 + d]  (pad 65: conflict-free)
    #pragma unroll
    for (int i = 0; i < (256 * 64) / NTHREADS; i++) {
        int flat = i * NTHREADS + tid;
        int p = flat >> 6, d = flat & 63;
        sm[SW1_OFF + p * 65 + d] = W1[flat];
    }
    sm[SB1_OFF + tid] = b1[tid];
    sm[SB2_OFF + tid] = b2[tid];
    sm[SW3_OFF + tid] = W3[tid];
    if (tid < MT) sm[SNN_OFF + tid] = 0.0f;
    #pragma unroll
    for (int i = 0; i < (MT * D_IN) / NTHREADS; i++) {
        int flat = i * NTHREADS + tid;
        sm[SS_OFF + flat] = S[m0 * D_IN + flat];
    }
    __syncthreads();

    // thread tiling: tm = sample-group (8 samples), th = output column group
    const int tm = tid >> 6;       // 0..3 (constant within a warp)
    const int th = tid & 63;       // 0..63
    const int mb = tm * 8;         // base sample within tile
    const int lane = tid & 31;

    float acc[8][4];

    // ---------------- Phase A: z1 = W1 s + b1 ; y1 = z1^2 ----------------
    #pragma unroll
    for (int i = 0; i < 8; i++)
        #pragma unroll
        for (int j = 0; j < 4; j++)
            acc[i][j] = sm[SB1_OFF + th + 64 * j];

    #pragma unroll
    for (int d4 = 0; d4 < 16; d4++) {
        float a_s[8][4];
        #pragma unroll
        for (int i = 0; i < 8; i++) {
            float4 a4 = *reinterpret_cast<const float4*>(&sm[SS_OFF + (mb + i) * D_IN + d4 * 4]);
            a_s[i][0] = a4.x; a_s[i][1] = a4.y; a_s[i][2] = a4.z; a_s[i][3] = a4.w;
        }
        #pragma unroll
        for (int c = 0; c < 4; c++) {
            int d = d4 * 4 + c;
            float b[4];
            #pragma unroll
            for (int j = 0; j < 4; j++) b[j] = sm[SW1_OFF + (th + 64 * j) * 65 + d];
            #pragma unroll
            for (int i = 0; i < 8; i++)
                #pragma unroll
                for (int j = 0; j < 4; j++)
                    acc[i][j] = fmaf(a_s[i][c], b[j], acc[i][j]);
        }
    }
    #pragma unroll
    for (int i = 0; i < 8; i++)
        #pragma unroll
        for (int j = 0; j < 4; j++) {
            float z = acc[i][j];
            int idx = (mb + i) * H_DIM + th + 64 * j;
            sm[SZ1_OFF + idx] = z;
            sm[SY1_OFF + idx] = z * z;
        }
    __syncthreads();

    // ---------------- Phase B: z2 = W2 y1 + b2 ; u = 2 W3 z2 ; nn += W3 z2^2 ----------------
    #pragma unroll
    for (int i = 0; i < 8; i++)
        #pragma unroll
        for (int j = 0; j < 4; j++)
            acc[i][j] = sm[SB2_OFF + th + 64 * j];

    for (int kc = 0; kc < H_DIM; kc += 32) {
        __syncthreads();
        // stage W2[h][kc..kc+31] -> sm[SW2_OFF + h*33 + kk]
        #pragma unroll
        for (int i = 0; i < 32; i++) {
            int flat = i * NTHREADS + tid;
            int h = flat >> 5, kk = flat & 31;
            sm[SW2_OFF + h * 33 + kk] = W2[h * H_DIM + kc + kk];
        }
        __syncthreads();
        #pragma unroll
        for (int kk4 = 0; kk4 < 8; kk4++) {
            float a_s[8][4];
            #pragma unroll
            for (int i = 0; i < 8; i++) {
                float4 a4 = *reinterpret_cast<const float4*>(
                    &sm[SY1_OFF + (mb + i) * H_DIM + kc + kk4 * 4]);
                a_s[i][0] = a4.x; a_s[i][1] = a4.y; a_s[i][2] = a4.z; a_s[i][3] = a4.w;
            }
            #pragma unroll
            for (int c = 0; c < 4; c++) {
                int kk = kk4 * 4 + c;
                float b[4];
                #pragma unroll
                for (int j = 0; j < 4; j++) b[j] = sm[SW2_OFF + (th + 64 * j) * 33 + kk];
                #pragma unroll
                for (int i = 0; i < 8; i++)
                    #pragma unroll
                    for (int j = 0; j < 4; j++)
                        acc[i][j] = fmaf(a_s[i][c], b[j], acc[i][j]);
            }
        }
    }
    // epilogue B
    {
        float pm[8];
        #pragma unroll
        for (int i = 0; i < 8; i++) {
            pm[i] = 0.0f;
            #pragma unroll
            for (int j = 0; j < 4; j++) {
                int h = th + 64 * j;
                float z2 = acc[i][j];
                float w3 = sm[SW3_OFF + h];
                sm[SU_OFF + (mb + i) * H_DIM + h] = 2.0f * w3 * z2;
                pm[i] = fmaf(w3 * z2, z2, pm[i]);
            }
        }
        #pragma unroll
        for (int off = 16; off > 0; off >>= 1)
            #pragma unroll
            for (int i = 0; i < 8; i++)
                pm[i] += __shfl_xor_sync(0xffffffffu, pm[i], off);
        if (lane == 0) {
            #pragma unroll
            for (int i = 0; i < 8; i++)
                atomicAdd(&sm[SNN_OFF + mb + i], pm[i]);
        }
    }
    __syncthreads();

    // ---------------- Phase D: t = u^T W2 (reduce over rows of W2) ; v = t * 2 z1 ----------------
    #pragma unroll
    for (int i = 0; i < 8; i++)
        #pragma unroll
        for (int j = 0; j < 4; j++)
            acc[i][j] = 0.0f;

    for (int hc = 0; hc < H_DIM; hc += 32) {
        __syncthreads();
        // stage W2[hc+hh][p] -> sm[SW2_OFF + hh*257 + p]
        #pragma unroll
        for (int i = 0; i < 32; i++) {
            int flat = i * NTHREADS + tid;
            int hh = flat >> 8, p = flat & 255;
            sm[SW2_OFF + hh * 257 + p] = W2[(hc + hh) * H_DIM + p];
        }
        __syncthreads();
        #pragma unroll
        for (int h4 = 0; h4 < 8; h4++) {
            float a_s[8][4];
            #pragma unroll
            for (int i = 0; i < 8; i++) {
                float4 a4 = *reinterpret_cast<const float4*>(
                    &sm[SU_OFF + (mb + i) * H_DIM + hc + h4 * 4]);
                a_s[i][0] = a4.x; a_s[i][1] = a4.y; a_s[i][2] = a4.z; a_s[i][3] = a4.w;
            }
            #pragma unroll
            for (int c = 0; c < 4; c++) {
                int hh = h4 * 4 + c;
                float b[4];
                #pragma unroll
                for (int j = 0; j < 4; j++) b[j] = sm[SW2_OFF + hh * 257 + th + 64 * j];
                #pragma unroll
                for (int i = 0; i < 8; i++)
                    #pragma unroll
                    for (int j = 0; j < 4; j++)
                        acc[i][j] = fmaf(a_s[i][c], b[j], acc[i][j]);
            }
        }
    }
    // epilogue D: v = t * 2*z1 -> overwrite sY1
    #pragma unroll
    for (int i = 0; i < 8; i++)
        #pragma unroll
        for (int j = 0; j < 4; j++) {
            int idx = (mb + i) * H_DIM + th + 64 * j;
            sm[SY1_OFF + idx] = acc[i][j] * 2.0f * sm[SZ1_OFF + idx];
        }
    __syncthreads();

    // ---------------- Phase E: grad = v^T W1  (reduce over rows of W1), th = d ----------------
    {
        float ga[8];
        #pragma unroll
        for (int i = 0; i < 8; i++) ga[i] = 0.0f;
        #pragma unroll
        for (int p4 = 0; p4 < 64; p4++) {
            float a_s[8][4];
            #pragma unroll
            for (int i = 0; i < 8; i++) {
                float4 a4 = *reinterpret_cast<const float4*>(
                    &sm[SY1_OFF + (mb + i) * H_DIM + p4 * 4]);
                a_s[i][0] = a4.x; a_s[i][1] = a4.y; a_s[i][2] = a4.z; a_s[i][3] = a4.w;
            }
            #pragma unroll
            for (int c = 0; c < 4; c++) {
                float b = sm[SW1_OFF + (p4 * 4 + c) * 65 + th];
                #pragma unroll
                for (int i = 0; i < 8; i++)
                    ga[i] = fmaf(a_s[i][c], b, ga[i]);
            }
        }
        #pragma unroll
        for (int i = 0; i < 8; i++)
            sm[SU_OFF + (mb + i) * D_IN + th] = ga[i];   // grad [MT][64] reuses sU
    }
    __syncthreads();

    // ---------------- Final epilogue ----------------
    {
        int m = tid >> 3, q = tid & 7;     // 8 threads per sample
        float c = 0.0f, sd = 0.0f, gd = 0.0f;
        #pragma unroll
        for (int r = 0; r < 8; r++) {
            int d = q + 8 * r;
            float s    = sm[SS_OFF + m * D_IN + d];
            float sdot = Sdot[(m0 + m) * D_IN + d];
            c  = fmaf(s, s, c);
            sd = fmaf(s, sdot, sd);
            gd = fmaf(sm[SU_OFF + m * D_IN + d], sdot, gd);
        }
        #pragma unroll
        for (int off = 4; off > 0; off >>= 1) {
            c  += __shfl_xor_sync(0xffffffffu, c,  off);
            sd += __shfl_xor_sync(0xffffffffu, sd, off);
            gd += __shfl_xor_sync(0xffffffffu, gd, off);
        }
        if (q == 0) {
            float nn = sm[SNN_OFF + m];
            out[m0 + m]              = nn * c;                         // V
            out[N_SAMP + m0 + m]     = 2.0f * nn * sd + c * gd;        // Vdot
            out[2 * N_SAMP + m0 + m] = c;                              // circle
        }
    }
}

extern "C" void kernel_launch(void* const* d_in, const int* in_sizes, int n_in,
                              void* d_out, int out_size)
{
    const float* S    = (const float*)d_in[0];
    const float* Sdot = (const float*)d_in[1];
    const float* W1   = (const float*)d_in[2];
    const float* b1   = (const float*)d_in[3];
    const float* W2   = (const float*)d_in[4];
    const float* b2   = (const float*)d_in[5];
    const float* W3   = (const float*)d_in[6];
    float* out = (float*)d_out;

    cudaFuncSetAttribute(learnerct_fused,
                         cudaFuncAttributeMaxDynamicSharedMemorySize, SMEM_BYTES);
    learnerct_fused<<<NBLOCKS, NTHREADS, SMEM_BYTES>>>(S, Sdot, W1, b1, W2, b2, W3, out);
}